// round 2
// baseline (speedup 1.0000x reference)
#include <cuda_runtime.h>

// Problem constants (fixed shapes from reference setup_inputs)
#define NVERT 6890
#define NFACE 13776
#define NB    16
#define BP    8
#define TT    (2*NFACE)        // 27552 triangles per person-pair
#define NC    65536            // collisions per person-pair
#define NPAIR (BP*NC)          // 524288
#define NBLK  (NPAIR/256)      // 2048 blocks in main kernel

#define SIGMA_INV 1e4f
#define EPSF      1e-9f
#define THRESH    2000.0f
#define WEIGHT    0.1f

// Scratch: device globals (no allocations allowed)
__device__ __align__(16) float4 g_verts4[NB*NVERT];     // vertex+trans, padded to float4
__device__ __align__(16) float4 g_intr[BP*TT*3];        // v0,v1,v2 packed (48B/tri)
__device__ __align__(32) float4 g_recv[BP*TT*2];        // {c.xyz, inv_r},{n.xyz,0} (32B/tri)
__device__ float g_partial[NBLK];

// ---------------------------------------------------------------------------
// Kernel A: vertices = verts + trans, padded to float4 for vectorized gathers
// ---------------------------------------------------------------------------
__global__ void k_verts(const float* __restrict__ verts,
                        const float* __restrict__ trans) {
    int i = blockIdx.x * blockDim.x + threadIdx.x;
    if (i >= NB * NVERT) return;
    int b = i / NVERT;
    float4 v;
    v.x = verts[3*i + 0] + trans[3*b + 0];
    v.y = verts[3*i + 1] + trans[3*b + 1];
    v.z = verts[3*i + 2] + trans[3*b + 2];
    v.w = 0.0f;
    g_verts4[i] = v;
}

// ---------------------------------------------------------------------------
// Kernel B: build per-triangle records (vertices + receiver frame)
// tri f of person-pair bp:  b = 2*bp + (f >= NFACE), face = f mod NFACE
// ---------------------------------------------------------------------------
__global__ void k_tri(const int* __restrict__ faces) {
    int t = blockIdx.x * blockDim.x + threadIdx.x;
    if (t >= BP * TT) return;
    int bp = t / TT;
    int f  = t - bp * TT;
    int p  = (f >= NFACE) ? 1 : 0;
    int b  = 2*bp + p;
    int face = f - p * NFACE;

    int ia = faces[3*face + 0];
    int ib = faces[3*face + 1];
    int ic = faces[3*face + 2];
    float4 v0 = g_verts4[b*NVERT + ia];
    float4 v1 = g_verts4[b*NVERT + ib];
    float4 v2 = g_verts4[b*NVERT + ic];

    // receiver frame: unit normal
    float e1x = v1.x - v0.x, e1y = v1.y - v0.y, e1z = v1.z - v0.z;
    float e2x = v2.x - v0.x, e2y = v2.y - v0.y, e2z = v2.z - v0.z;
    float nx = e1y*e2z - e1z*e2y;
    float ny = e1z*e2x - e1x*e2z;
    float nz = e1x*e2y - e1y*e2x;
    float nl = sqrtf(nx*nx + ny*ny + nz*nz);
    float inv_n = __fdividef(1.0f, nl + EPSF);
    nx *= inv_n; ny *= inv_n; nz *= inv_n;

    // centroid + circumscribed radius
    float cx = (v0.x + v1.x + v2.x) * (1.0f/3.0f);
    float cy = (v0.y + v1.y + v2.y) * (1.0f/3.0f);
    float cz = (v0.z + v1.z + v2.z) * (1.0f/3.0f);
    float dx0 = v0.x-cx, dy0 = v0.y-cy, dz0 = v0.z-cz;
    float dx1 = v1.x-cx, dy1 = v1.y-cy, dz1 = v1.z-cz;
    float dx2 = v2.x-cx, dy2 = v2.y-cy, dz2 = v2.z-cz;
    float r2 = dx0*dx0 + dy0*dy0 + dz0*dz0;
    float q  = dx1*dx1 + dy1*dy1 + dz1*dz1; if (q > r2) r2 = q;
    q        = dx2*dx2 + dy2*dy2 + dz2*dz2; if (q > r2) r2 = q;
    float inv_r = __fdividef(1.0f, sqrtf(r2) + EPSF);

    float4 cr; cr.x = cx; cr.y = cy; cr.z = cz; cr.w = inv_r;
    float4 nn; nn.x = nx; nn.y = ny; nn.z = nz; nn.w = 0.0f;
    g_recv[2*t + 0] = cr;
    g_recv[2*t + 1] = nn;

    float4 i0; i0.x = v0.x; i0.y = v0.y; i0.z = v0.z; i0.w = v1.x;
    float4 i1; i1.x = v1.y; i1.y = v1.z; i1.z = v2.x; i1.w = v2.y;
    float4 i2; i2.x = v2.z; i2.y = 0.0f; i2.z = 0.0f; i2.w = 0.0f;
    g_intr[3*t + 0] = i0;
    g_intr[3*t + 1] = i1;
    g_intr[3*t + 2] = i2;
}

// ---------------------------------------------------------------------------
// Main kernel: one thread per collision pair; block-level deterministic reduce
// ---------------------------------------------------------------------------
__global__ void k_pairs(const int2* __restrict__ coll) {
    int gid = blockIdx.x * blockDim.x + threadIdx.x;
    int bp  = gid >> 16;                // NC = 65536 per person-pair
    int base = bp * TT;

    int2 ci = coll[gid];
    float acc = 0.0f;
    if (ci.x != ci.y) {
        const float4* R = &g_recv[2*(base + ci.y)];
        float4 cr = R[0];
        float4 nn = R[1];
        const float4* I = &g_intr[3*(base + ci.x)];
        float4 A  = I[0];
        float4 Bq = I[1];
        float4 Cq = I[2];

        float vx[3] = {A.x, A.w, Bq.z};
        float vy[3] = {A.y, Bq.x, Bq.w};
        float vz[3] = {A.z, Bq.y, Cq.x};
        #pragma unroll
        for (int k = 0; k < 3; k++) {
            float dx = vx[k] - cr.x;
            float dy = vy[k] - cr.y;
            float dz = vz[k] - cr.z;
            float d  = dx*nn.x + dy*nn.y + dz*nn.z;
            if (d < 0.0f) {                       // relu(-d/sigma) > 0
                float px = dx - d*nn.x;
                float py = dy - d*nn.y;
                float pz = dz - d*nn.z;
                float radial = sqrtf(px*px + py*py + pz*pz);
                float t2 = 1.0f - radial * cr.w;  // cr.w = 1/(radius+eps)
                if (t2 > 0.0f) {
                    float fld = (-d * SIGMA_INV) * t2;
                    acc += fld * fld;
                }
            }
        }
    }

    __shared__ float sd[256];
    sd[threadIdx.x] = acc;
    __syncthreads();
    #pragma unroll
    for (int s = 128; s > 0; s >>= 1) {
        if (threadIdx.x < s) sd[threadIdx.x] += sd[threadIdx.x + s];
        __syncthreads();
    }
    if (threadIdx.x == 0) g_partial[blockIdx.x] = sd[0];
}

// ---------------------------------------------------------------------------
// Final kernel: per-bp pen sums (fixed order) + scalar epilogue
// ---------------------------------------------------------------------------
__global__ void k_final(float* __restrict__ out) {
    int tid  = threadIdx.x;
    int w    = tid >> 5;     // warp = person-pair index (8 warps)
    int lane = tid & 31;
    __shared__ float spen[BP];

    float s = 0.0f;
    #pragma unroll
    for (int k = 0; k < 8; k++)
        s += g_partial[w*256 + k*32 + lane];   // 256 block partials per bp
    #pragma unroll
    for (int o = 16; o > 0; o >>= 1)
        s += __shfl_down_sync(0xffffffffu, s, o);
    if (lane == 0) spen[w] = s;
    __syncthreads();

    if (tid == 0) {
        float cnt = 0.0f, vsum = 0.0f;
        #pragma unroll
        for (int bp = 0; bp < BP; bp++) {
            float pen = spen[bp];
            if (pen < THRESH) {
                cnt  += 1.0f;
                float sg = __fdividef(1.0f, 1.0f + __expf(-pen * (1.0f/THRESH)));
                vsum += sg - 0.5f;
            }
        }
        out[0] = (cnt > 0.0f) ? (vsum / cnt) * WEIGHT : 0.0f;
    }
}

// ---------------------------------------------------------------------------
extern "C" void kernel_launch(void* const* d_in, const int* in_sizes, int n_in,
                              void* d_out, int out_size) {
    const float* verts = (const float*)d_in[0];   // [16, 6890, 3] f32
    const float* trans = (const float*)d_in[1];   // [16, 3] f32
    const int*   faces = (const int*)d_in[2];     // [13776, 3] i32
    const int2*  coll  = (const int2*)d_in[3];    // [8, 65536, 2] i32

    k_verts<<<(NB*NVERT + 255)/256, 256>>>(verts, trans);
    k_tri  <<<(BP*TT   + 255)/256, 256>>>(faces);
    k_pairs<<<NBLK, 256>>>(coll);
    k_final<<<1, 256>>>((float*)d_out);
}